// round 4
// baseline (speedup 1.0000x reference)
#include <cuda_runtime.h>
#include <cuda_bf16.h>

// YOLO loss: pred [16384,7,7,30] f32, target [16384,7,7,30] f32 -> scalar f32.
// Pure HBM-bound reduction (192.6 MB in, 4 B out).
//
// Grid-stride blocks with 2-stage cp.async double buffer: loads for chunk i+1
// are issued before waiting on chunk i, keeping ~30KB per block in flight at
// all times. 3 blocks/SM (61.4KB dyn smem each). Register accumulation across
// chunks, one block reduction, last-block-done final reduce (deterministic).

#define S 7
#define CELLS_PER_IMG 49
#define NCH 30
#define BATCH 16384
#define TOTAL_CELLS (BATCH * CELLS_PER_IMG)    // 802816
#define BLOCK_CELLS 128
#define NCHUNKS (TOTAL_CELLS / BLOCK_CELLS)    // 6272
#define GRID 444                               // 148 SMs * 3
#define CHUNK_FLOATS (BLOCK_CELLS * NCH)       // 3840
#define CHUNK_F4 (CHUNK_FLOATS / 4)            // 960
#define STAGE_FLOATS (2 * CHUNK_FLOATS)        // pred + tgt per stage
#define SMEM_BYTES (2 * STAGE_FLOATS * 4)      // 61440
#define STEP (1.0f / 7.0f)
#define LAMBDA_COORD 5.0f
#define LAMBDA_NOOBJ 0.5f

__device__ float g_partials[GRID];
__device__ unsigned int g_count;   // zero-init; reset by last block each launch

struct Box { float x1, y1, x2, y2; };

__device__ __forceinline__ Box convert_box(float x, float y, float w, float h,
                                           float gi, float gj) {
    float cx = (x + gi) * STEP;
    float cy = (y + gj) * STEP;
    Box b;
    b.x1 = fmaxf(cx - 0.5f * w, 0.0f);
    b.y1 = fmaxf(cy - 0.5f * h, 0.0f);
    b.x2 = fminf(cx + 0.5f * w, 1.0f);
    b.y2 = fminf(cy + 0.5f * h, 1.0f);
    return b;
}

__device__ __forceinline__ float iou(const Box& t, const Box& p) {
    // Faithful to reference: inter not clamped; zero if inter <= 0.
    float minx = fmaxf(t.x1, p.x1);
    float miny = fmaxf(t.y1, p.y1);
    float maxx = fminf(t.x2, p.x2);
    float maxy = fminf(t.y2, p.y2);
    float inter = (maxy - miny) * (maxx - minx);
    float uni = (p.x2 - p.x1) * (p.y2 - p.y1)
              + (t.y2 - t.y1) * (t.x2 - t.x1) - inter;
    return (inter > 0.0f) ? inter / (uni + 1e-05f) : 0.0f;
}

__device__ __forceinline__ void cp_async16(float* smem_dst, const float4* gsrc) {
    unsigned int saddr = (unsigned int)__cvta_generic_to_shared(smem_dst);
    asm volatile("cp.async.cg.shared.global [%0], [%1], 16;\n"
                 :: "r"(saddr), "l"(gsrc) : "memory");
}

__device__ __forceinline__ void issue_chunk(int chunk, float* sbuf,
                                            const float* __restrict__ pred,
                                            const float* __restrict__ tgt,
                                            int tid) {
    const size_t base = (size_t)chunk * CHUNK_FLOATS;
    const float4* p4 = reinterpret_cast<const float4*>(pred + base);
    const float4* t4 = reinterpret_cast<const float4*>(tgt + base);
    float* sp = sbuf;                  // pred half
    float* st = sbuf + CHUNK_FLOATS;   // tgt half
#pragma unroll
    for (int i = 0; i < 8; i++) {
        int idx = tid + i * BLOCK_CELLS;
        if (idx < CHUNK_F4) {
            cp_async16(sp + idx * 4, p4 + idx);
            cp_async16(st + idx * 4, t4 + idx);
        }
    }
    asm volatile("cp.async.commit_group;\n" ::: "memory");
}

__global__ void __launch_bounds__(BLOCK_CELLS)
yolo_loss_pipe(const float* __restrict__ pred, const float* __restrict__ tgt,
               float* __restrict__ out) {
    extern __shared__ float sbuf[];    // 2 stages * (pred+tgt chunk)
    __shared__ float wsum[BLOCK_CELLS / 32];
    __shared__ int s_islast;

    const int tid = threadIdx.x;
    float acc = 0.0f;

    int c = blockIdx.x;
    if (c < NCHUNKS)
        issue_chunk(c, sbuf, pred, tgt, tid);

    int it = 0;
    for (; c < NCHUNKS; c += GRID, it++) {
        const int b = it & 1;
        const int nc = c + GRID;
        if (nc < NCHUNKS) {
            issue_chunk(nc, sbuf + (b ^ 1) * STAGE_FLOATS, pred, tgt, tid);
            asm volatile("cp.async.wait_group 1;\n" ::: "memory");
        } else {
            asm volatile("cp.async.wait_group 0;\n" ::: "memory");
        }
        __syncthreads();

        const float* P = sbuf + b * STAGE_FLOATS + tid * NCH;
        const float* T = sbuf + b * STAGE_FLOATS + CHUNK_FLOATS + tid * NCH;

        const int cell = c * BLOCK_CELLS + tid;
        const int r = cell % CELLS_PER_IMG;
        const float gi = (float)(r / S);
        const float gj = (float)(r % S);

        const float t0 = T[0], t1 = T[1], t2 = T[2], t3 = T[3], tconf = T[4];
        Box tb = convert_box(t0, t1, t2, t3, gi, gj);
        Box pb1 = convert_box(P[0], P[1], P[2], P[3], gi, gj);
        Box pb2 = convert_box(P[5], P[6], P[7], P[8], gi, gj);
        float iou1 = iou(tb, pb1);
        float iou2 = iou(tb, pb2);

        bool sel2 = (iou1 <= iou2);
        float conf_t = sel2 ? iou2 : iou1;
        float px = sel2 ? P[5] : P[0];
        float py = sel2 ? P[6] : P[1];
        float pw = sel2 ? P[7] : P[2];
        float ph = sel2 ? P[8] : P[3];
        float pconf = sel2 ? P[9] : P[4];

        float obj = (tconf > 0.0f) ? 1.0f : 0.0f;
        float noobj = (tconf == 0.0f) ? 1.0f : 0.0f;

        float dconf = pconf - conf_t;
        float dx = px - t0, dy = py - t1, dw = pw - t2, dh = ph - t3;
        float coord = dx * dx + dy * dy + dw * dw + dh * dh;

        float cls = 0.0f;
#pragma unroll
        for (int k = 10; k < NCH; k++) {
            float d = P[k] - T[k];
            cls = fmaf(d, d, cls);
        }

        float d4 = P[4] - T[4];
        float d9 = P[9] - T[9];
        float noobj_term = d4 * d4 + d9 * d9;

        acc += obj * (dconf * dconf + LAMBDA_COORD * coord + cls)
             + LAMBDA_NOOBJ * noobj * noobj_term;

        __syncthreads();   // protect buffer b: next iteration issues into it
    }

    // Single block reduction.
#pragma unroll
    for (int off = 16; off > 0; off >>= 1)
        acc += __shfl_down_sync(0xFFFFFFFFu, acc, off);
    if ((tid & 31) == 0) wsum[tid >> 5] = acc;
    __syncthreads();

    if (tid == 0) {
        float s = wsum[0];
#pragma unroll
        for (int w = 1; w < BLOCK_CELLS / 32; w++) s += wsum[w];
        g_partials[blockIdx.x] = s;
        __threadfence();
        unsigned int old = atomicAdd(&g_count, 1u);
        s_islast = (old == GRID - 1u) ? 1 : 0;
    }
    __syncthreads();

    if (s_islast) {
        // Fixed-order final reduce by the last block (deterministic).
        volatile float* vp = g_partials;
        float s = 0.0f;
        for (int i = tid; i < GRID; i += BLOCK_CELLS) s += vp[i];
#pragma unroll
        for (int off = 16; off > 0; off >>= 1)
            s += __shfl_down_sync(0xFFFFFFFFu, s, off);
        if ((tid & 31) == 0) wsum[tid >> 5] = s;
        __syncthreads();
        if (tid == 0) {
            float tot = wsum[0];
#pragma unroll
            for (int w = 1; w < BLOCK_CELLS / 32; w++) tot += wsum[w];
            out[0] = tot * (1.0f / (float)BATCH);
            __threadfence();
            g_count = 0u;   // reset for next graph replay
        }
    }
}

extern "C" void kernel_launch(void* const* d_in, const int* in_sizes, int n_in,
                              void* d_out, int out_size) {
    const float* pred = (const float*)d_in[0];
    const float* tgt  = (const float*)d_in[1];
    float* out = (float*)d_out;

    cudaFuncSetAttribute(yolo_loss_pipe,
                         cudaFuncAttributeMaxDynamicSharedMemorySize,
                         SMEM_BYTES);
    yolo_loss_pipe<<<GRID, BLOCK_CELLS, SMEM_BYTES>>>(pred, tgt, out);
}

// round 5
// speedup vs baseline: 1.0652x; 1.0652x over previous
#include <cuda_runtime.h>
#include <cuda_bf16.h>
#include <cstdint>

// YOLO loss: pred [16384,7,7,30] f32, target [16384,7,7,30] f32 -> scalar f32.
// Pure HBM-bound reduction (192.6 MB in, 4 B out).
//
// R5: identical structure to R4 (grid-stride, 2-stage double buffer, fused
// last-block-done tail) but staging via cp.async.bulk (TMA/UBLKCP): one
// instruction per 15360B tensor-chunk, mbarrier complete_tx completion.
// This replaces per-lane 16B LSU requests with autonomous TMA line streaming.

#define S 7
#define CELLS_PER_IMG 49
#define NCH 30
#define BATCH 16384
#define TOTAL_CELLS (BATCH * CELLS_PER_IMG)    // 802816
#define BLOCK_CELLS 128
#define NCHUNKS (TOTAL_CELLS / BLOCK_CELLS)    // 6272
#define GRID 444                               // 148 SMs * 3
#define CHUNK_FLOATS (BLOCK_CELLS * NCH)       // 3840
#define CHUNK_BYTES (CHUNK_FLOATS * 4)         // 15360
#define STAGE_FLOATS (2 * CHUNK_FLOATS)        // pred + tgt
#define STAGE_BYTES (2 * CHUNK_BYTES)          // 30720
#define SMEM_BYTES (2 * STAGE_BYTES)           // 61440
#define STEP (1.0f / 7.0f)
#define LAMBDA_COORD 5.0f
#define LAMBDA_NOOBJ 0.5f

__device__ float g_partials[GRID];
__device__ unsigned int g_count;   // zero-init; reset by last block each launch

struct Box { float x1, y1, x2, y2; };

__device__ __forceinline__ Box convert_box(float x, float y, float w, float h,
                                           float gi, float gj) {
    float cx = (x + gi) * STEP;
    float cy = (y + gj) * STEP;
    Box b;
    b.x1 = fmaxf(cx - 0.5f * w, 0.0f);
    b.y1 = fmaxf(cy - 0.5f * h, 0.0f);
    b.x2 = fminf(cx + 0.5f * w, 1.0f);
    b.y2 = fminf(cy + 0.5f * h, 1.0f);
    return b;
}

__device__ __forceinline__ float iou(const Box& t, const Box& p) {
    // Faithful to reference: inter not clamped; zero if inter <= 0.
    float minx = fmaxf(t.x1, p.x1);
    float miny = fmaxf(t.y1, p.y1);
    float maxx = fminf(t.x2, p.x2);
    float maxy = fminf(t.y2, p.y2);
    float inter = (maxy - miny) * (maxx - minx);
    float uni = (p.x2 - p.x1) * (p.y2 - p.y1)
              + (t.y2 - t.y1) * (t.x2 - t.x1) - inter;
    return (inter > 0.0f) ? inter / (uni + 1e-05f) : 0.0f;
}

__device__ __forceinline__ uint32_t smem_u32(const void* p) {
    return (uint32_t)__cvta_generic_to_shared(p);
}

__device__ __forceinline__ void mbar_init(uint32_t mbar, uint32_t count) {
    asm volatile("mbarrier.init.shared.b64 [%0], %1;" :: "r"(mbar), "r"(count)
                 : "memory");
}

__device__ __forceinline__ void mbar_expect_tx(uint32_t mbar, uint32_t bytes) {
    asm volatile("mbarrier.arrive.expect_tx.shared.b64 _, [%0], %1;"
                 :: "r"(mbar), "r"(bytes) : "memory");
}

__device__ __forceinline__ void bulk_g2s(uint32_t sdst, const void* gsrc,
                                         uint32_t bytes, uint32_t mbar) {
    asm volatile(
        "cp.async.bulk.shared::cta.global.mbarrier::complete_tx::bytes "
        "[%0], [%1], %2, [%3];"
        :: "r"(sdst), "l"(gsrc), "r"(bytes), "r"(mbar) : "memory");
}

__device__ __forceinline__ void mbar_wait(uint32_t mbar, uint32_t parity) {
    asm volatile(
        "{\n\t"
        ".reg .pred P;\n\t"
        "WAIT_%=: \n\t"
        "mbarrier.try_wait.parity.acquire.cta.shared::cta.b64 P, [%0], %1, 0x989680;\n\t"
        "@P bra.uni DONE_%=;\n\t"
        "bra.uni WAIT_%=;\n\t"
        "DONE_%=: \n\t"
        "}"
        :: "r"(mbar), "r"(parity) : "memory");
}

__global__ void __launch_bounds__(BLOCK_CELLS)
yolo_loss_tma(const float* __restrict__ pred, const float* __restrict__ tgt,
              float* __restrict__ out) {
    extern __shared__ __align__(128) float sbuf[];   // 2 stages, 61440 B
    __shared__ __align__(8) uint64_t mbar_s[2];
    __shared__ float wsum[BLOCK_CELLS / 32];
    __shared__ int s_islast;

    const int tid = threadIdx.x;
    const uint32_t mbar0 = smem_u32(&mbar_s[0]);
    const uint32_t mbar1 = smem_u32(&mbar_s[1]);

    if (tid == 0) {
        mbar_init(mbar0, 1);
        mbar_init(mbar1, 1);
    }
    __syncthreads();

    // Prologue: issue chunks for iterations 0 and 1.
    if (tid == 0) {
        int c0 = blockIdx.x;
        if (c0 < NCHUNKS) {
            mbar_expect_tx(mbar0, STAGE_BYTES);
            bulk_g2s(smem_u32(sbuf), pred + (size_t)c0 * CHUNK_FLOATS,
                     CHUNK_BYTES, mbar0);
            bulk_g2s(smem_u32(sbuf + CHUNK_FLOATS),
                     tgt + (size_t)c0 * CHUNK_FLOATS, CHUNK_BYTES, mbar0);
        }
        int c1 = c0 + GRID;
        if (c1 < NCHUNKS) {
            mbar_expect_tx(mbar1, STAGE_BYTES);
            bulk_g2s(smem_u32(sbuf + STAGE_FLOATS),
                     pred + (size_t)c1 * CHUNK_FLOATS, CHUNK_BYTES, mbar1);
            bulk_g2s(smem_u32(sbuf + STAGE_FLOATS + CHUNK_FLOATS),
                     tgt + (size_t)c1 * CHUNK_FLOATS, CHUNK_BYTES, mbar1);
        }
    }

    float acc = 0.0f;
    int ph0 = 0, ph1 = 0;
    int it = 0;
    for (int c = blockIdx.x; c < NCHUNKS; c += GRID, it++) {
        const int b = it & 1;
        if (b == 0) { mbar_wait(mbar0, ph0); ph0 ^= 1; }
        else        { mbar_wait(mbar1, ph1); ph1 ^= 1; }

        const float* P = sbuf + b * STAGE_FLOATS + tid * NCH;
        const float* T = sbuf + b * STAGE_FLOATS + CHUNK_FLOATS + tid * NCH;

        const int cell = c * BLOCK_CELLS + tid;
        const int r = cell % CELLS_PER_IMG;
        const float gi = (float)(r / S);
        const float gj = (float)(r % S);

        const float t0 = T[0], t1 = T[1], t2 = T[2], t3 = T[3], tconf = T[4];
        Box tb = convert_box(t0, t1, t2, t3, gi, gj);
        Box pb1 = convert_box(P[0], P[1], P[2], P[3], gi, gj);
        Box pb2 = convert_box(P[5], P[6], P[7], P[8], gi, gj);
        float iou1 = iou(tb, pb1);
        float iou2 = iou(tb, pb2);

        bool sel2 = (iou1 <= iou2);
        float conf_t = sel2 ? iou2 : iou1;
        float px = sel2 ? P[5] : P[0];
        float py = sel2 ? P[6] : P[1];
        float pw = sel2 ? P[7] : P[2];
        float ph = sel2 ? P[8] : P[3];
        float pconf = sel2 ? P[9] : P[4];

        float obj = (tconf > 0.0f) ? 1.0f : 0.0f;
        float noobj = (tconf == 0.0f) ? 1.0f : 0.0f;

        float dconf = pconf - conf_t;
        float dx = px - t0, dy = py - t1, dw = pw - t2, dh = ph - t3;
        float coord = dx * dx + dy * dy + dw * dw + dh * dh;

        float cls = 0.0f;
#pragma unroll
        for (int k = 10; k < NCH; k++) {
            float d = P[k] - T[k];
            cls = fmaf(d, d, cls);
        }

        float d4 = P[4] - T[4];
        float d9 = P[9] - T[9];
        float noobj_term = d4 * d4 + d9 * d9;

        acc += obj * (dconf * dconf + LAMBDA_COORD * coord + cls)
             + LAMBDA_NOOBJ * noobj * noobj_term;

        __syncthreads();   // all threads done reading buffer b

        const int nc = c + 2 * GRID;
        if (tid == 0 && nc < NCHUNKS) {
            const uint32_t mb = b ? mbar1 : mbar0;
            mbar_expect_tx(mb, STAGE_BYTES);
            bulk_g2s(smem_u32(sbuf + b * STAGE_FLOATS),
                     pred + (size_t)nc * CHUNK_FLOATS, CHUNK_BYTES, mb);
            bulk_g2s(smem_u32(sbuf + b * STAGE_FLOATS + CHUNK_FLOATS),
                     tgt + (size_t)nc * CHUNK_FLOATS, CHUNK_BYTES, mb);
        }
    }

    // Single block reduction.
#pragma unroll
    for (int off = 16; off > 0; off >>= 1)
        acc += __shfl_down_sync(0xFFFFFFFFu, acc, off);
    if ((tid & 31) == 0) wsum[tid >> 5] = acc;
    __syncthreads();

    if (tid == 0) {
        float s = wsum[0];
#pragma unroll
        for (int w = 1; w < BLOCK_CELLS / 32; w++) s += wsum[w];
        g_partials[blockIdx.x] = s;
        __threadfence();
        unsigned int old = atomicAdd(&g_count, 1u);
        s_islast = (old == GRID - 1u) ? 1 : 0;
    }
    __syncthreads();

    if (s_islast) {
        // Fixed-order final reduce by the last block (deterministic).
        volatile float* vp = g_partials;
        float s = 0.0f;
        for (int i = tid; i < GRID; i += BLOCK_CELLS) s += vp[i];
#pragma unroll
        for (int off = 16; off > 0; off >>= 1)
            s += __shfl_down_sync(0xFFFFFFFFu, s, off);
        if ((tid & 31) == 0) wsum[tid >> 5] = s;
        __syncthreads();
        if (tid == 0) {
            float tot = wsum[0];
#pragma unroll
            for (int w = 1; w < BLOCK_CELLS / 32; w++) tot += wsum[w];
            out[0] = tot * (1.0f / (float)BATCH);
            __threadfence();
            g_count = 0u;   // reset for next graph replay
        }
    }
}

extern "C" void kernel_launch(void* const* d_in, const int* in_sizes, int n_in,
                              void* d_out, int out_size) {
    const float* pred = (const float*)d_in[0];
    const float* tgt  = (const float*)d_in[1];
    float* out = (float*)d_out;

    cudaFuncSetAttribute(yolo_loss_tma,
                         cudaFuncAttributeMaxDynamicSharedMemorySize,
                         SMEM_BYTES);
    yolo_loss_tma<<<GRID, BLOCK_CELLS, SMEM_BYTES>>>(pred, tgt, out);
}